// round 14
// baseline (speedup 1.0000x reference)
#include <cuda_runtime.h>
#include <math.h>
#include <stdint.h>

#define NMAX 65536
#define EMAX (1 << 20)
#define HD   128

typedef unsigned long long u64;

// ----- scratch -----
__device__ int   g_deg[NMAX];
__device__ int   g_rowptr[NMAX];
__device__ int   g_cursor[NMAX];
__device__ int   g_bsum[256];
__device__ int   g_ssrc[EMAX];          // src sorted by dst
__device__ int   g_sdst[EMAX];          // dst sorted
__device__ float g_eas[EMAX * 16];      // edge_attr permuted to sorted order
__device__ float g_agg1[NMAX * 32];
__device__ float g_h   [NMAX * HD];
__device__ float g_agg2[NMAX * HD];     // reused as nh2 at the end
__device__ float g_h2  [NMAX * HD];
__device__ float g_t1  [NMAX * HD];
__device__ float g_pooled[64 * HD];

__device__ __forceinline__ float leakyf(float v) { return v > 0.f ? v : 0.01f * v; }

__device__ __forceinline__ u64 pack2(float lo, float hi) {
    u64 r; asm("mov.b64 %0, {%1, %2};" : "=l"(r) : "f"(lo), "f"(hi)); return r;
}
__device__ __forceinline__ void unpack2(float& lo, float& hi, u64 v) {
    asm("mov.b64 {%0, %1}, %2;" : "=f"(lo), "=f"(hi) : "l"(v));
}
__device__ __forceinline__ u64 fma2(u64 a, u64 b, u64 c) {
    u64 d; asm("fma.rn.f32x2 %0, %1, %2, %3;" : "=l"(d) : "l"(a), "l"(b), "l"(c)); return d;
}

// ---------------------------------------------------------------------------
// zero_all: deg + agg1 + agg2 in one launch (int4/float4 stores)
// ---------------------------------------------------------------------------
__global__ void zero_all(int* __restrict__ deg, float* __restrict__ agg1,
                         float* __restrict__ agg2, int N)
{
    int j = blockIdx.x * 256 + threadIdx.x;
    int n1 = N * 32 / 4, n2 = N * 128 / 4, nd = N / 4;
    float4 z = make_float4(0.f, 0.f, 0.f, 0.f);
    if (j < n1) ((float4*)agg1)[j] = z;
    else if (j < n1 + n2) ((float4*)agg2)[j - n1] = z;
    else if (j < n1 + n2 + nd) ((int4*)deg)[j - n1 - n2] = make_int4(0, 0, 0, 0);
}

// ---------------------------------------------------------------------------
// CSR build: histogram -> scan -> scan23 -> scatter(+payload permute)
// ---------------------------------------------------------------------------
__global__ void hist_k(const int* __restrict__ dst, int* __restrict__ deg, int E)
{
    int e = blockIdx.x * 256 + threadIdx.x;
    if (e < E) atomicAdd(&deg[dst[e]], 1);
}

__global__ void scan1_k(const int* __restrict__ deg, int* __restrict__ rowptr,
                        int* __restrict__ bsum, int N)
{
    __shared__ int s[256];
    int t = threadIdx.x;
    int i = blockIdx.x * 256 + t;
    int v = (i < N) ? deg[i] : 0;
    s[t] = v;
    __syncthreads();
    for (int off = 1; off < 256; off <<= 1) {
        int tv = (t >= off) ? s[t - off] : 0;
        __syncthreads();
        s[t] += tv;
        __syncthreads();
    }
    if (i < N) rowptr[i] = s[t] - v;            // exclusive within block
    if (t == 255) bsum[blockIdx.x] = s[255];
}

// every block scans bsum itself, then applies its own exclusive offset
__global__ void scan23_k(int* __restrict__ rowptr, const int* __restrict__ bsum,
                         int* __restrict__ cursor, int N, int nb)
{
    __shared__ int s[256];
    int t = threadIdx.x;
    int v = (t < nb) ? bsum[t] : 0;
    s[t] = v;
    __syncthreads();
    for (int off = 1; off < 256; off <<= 1) {
        int tv = (t >= off) ? s[t - off] : 0;
        __syncthreads();
        s[t] += tv;
        __syncthreads();
    }
    __syncthreads();
    int b = blockIdx.x;
    int boff = s[b] - bsum[b];                  // exclusive offset for this block
    int i = b * 256 + t;
    if (i < N) {
        int r = rowptr[i] + boff;
        rowptr[i] = r;
        cursor[i] = r;
    }
}

// scatter + payload permute: ssrc/sdst/ea_s all in sorted order
__global__ void scatter_k(const int* __restrict__ src, const int* __restrict__ dst,
                          const float* __restrict__ ea, int* __restrict__ cursor,
                          int* __restrict__ ssrc, int* __restrict__ sdst,
                          float* __restrict__ eas, int E)
{
    int e = blockIdx.x * 256 + threadIdx.x;
    if (e < E) {
        int d = dst[e];
        int p = atomicAdd(&cursor[d], 1);
        ssrc[p] = src[e];
        sdst[p] = d;
        const float4* er = (const float4*)(ea + (size_t)e * 16);
        float4* ew = (float4*)(eas + (size_t)p * 16);
        ew[0] = er[0]; ew[1] = er[1]; ew[2] = er[2]; ew[3] = er[3];
    }
}

// ---------------------------------------------------------------------------
// Edge layer 1, SORTED+COALESCED: segment-accumulate, RED at dst boundaries.
// One warp / 32 sorted edges; lane owns 1 of 32 channels. W in regs.
// ---------------------------------------------------------------------------
#define E1_CHUNK 32
__global__ __launch_bounds__(256)
void edge1_kernel(const float* __restrict__ x, const int* __restrict__ ssrc,
                  const int* __restrict__ sdst, const float* __restrict__ eas,
                  const float* __restrict__ W, const float* __restrict__ bias,
                  float* __restrict__ agg, int E)
{
    int lane = threadIdx.x & 31;
    int warp = blockIdx.x * 8 + (threadIdx.x >> 5);
    int base = warp * E1_CHUNK;
    if (base >= E) return;

    float w[16];
    #pragma unroll
    for (int k = 0; k < 16; k++) w[k] = __ldg(&W[k * 32 + lane]);
    float b = __ldg(&bias[lane]);

    int sA = __ldg(&ssrc[base + lane]);
    int dv = __ldg(&sdst[base + lane]);

    float acc = 0.f;
    #pragma unroll 4
    for (int i = 0; i < E1_CHUNK; i++) {
        int s  = __shfl_sync(0xffffffffu, sA, i);
        int d  = __shfl_sync(0xffffffffu, dv, i);
        int dn = (i < E1_CHUNK - 1) ? __shfl_sync(0xffffffffu, dv, i + 1) : -1;
        float av = (lane < 16) ? __ldg(&eas[(size_t)(base + i) * 16 + lane]) : 0.f;
        float g = __ldg(&x[(size_t)s * 32 + lane]);
        float t = b;
        #pragma unroll
        for (int k = 0; k < 16; k++)
            t = fmaf(__shfl_sync(0xffffffffu, av, k), w[k], t);
        acc += fmaxf(t + g, 0.f);
        if (dn != d) {
            asm volatile("red.global.add.f32 [%0], %1;"
                         :: "l"(agg + (size_t)d * 32 + lane), "f"(acc) : "memory");
            acc = 0.f;
        }
    }
}

// ---------------------------------------------------------------------------
// Edge layer 2, SORTED+COALESCED: 2 warps / 16-edge chunk, 64 ch per warp.
// Segment-accumulate, RED.v2 at dst boundaries. W in regs (f32x2).
// ---------------------------------------------------------------------------
#define E2_CHUNK 16
__global__ __launch_bounds__(256, 4)
void edge2_kernel(const float* __restrict__ h, const int* __restrict__ ssrc,
                  const int* __restrict__ sdst, const float* __restrict__ eas,
                  const float* __restrict__ W, const float* __restrict__ bias,
                  float* __restrict__ agg, int E)
{
    int lane = threadIdx.x & 31;
    int warp = blockIdx.x * 8 + (threadIdx.x >> 5);
    int chunk = warp >> 1;
    int half  = warp & 1;
    int base = chunk * E2_CHUNK;
    if (base >= E) return;
    int ch = half * 64 + lane * 2;

    u64 w2[16];
    #pragma unroll
    for (int k = 0; k < 16; k++) {
        float2 wv = *(const float2*)(W + (size_t)k * 128 + ch);
        w2[k] = pack2(wv.x, wv.y);
    }
    float2 bv = *(const float2*)(bias + ch);
    u64 b2 = pack2(bv.x, bv.y);

    int li = lane & 15;
    int sv = (lane < 16) ? __ldg(&ssrc[base + li]) : 0;
    int dv = (lane >= 16) ? __ldg(&sdst[base + li]) : 0;

    float accx = 0.f, accy = 0.f;
    for (int i = 0; i < E2_CHUNK; i++) {
        int s  = __shfl_sync(0xffffffffu, sv, i);
        int d  = __shfl_sync(0xffffffffu, dv, 16 + i);
        int dn = (i < E2_CHUNK - 1) ? __shfl_sync(0xffffffffu, dv, 16 + i + 1) : -1;
        float av = (lane < 16) ? __ldg(&eas[(size_t)(base + i) * 16 + lane]) : 0.f;
        float2 g = *(const float2*)(h + (size_t)s * HD + ch);

        u64 tE = b2, tO = 0ull;
        #pragma unroll
        for (int k = 0; k < 16; k += 2) {
            float a0 = __shfl_sync(0xffffffffu, av, k);
            float a1 = __shfl_sync(0xffffffffu, av, k + 1);
            tE = fma2(pack2(a0, a0), w2[k],     tE);
            tO = fma2(pack2(a1, a1), w2[k + 1], tO);
        }
        float tx, ty, ux, uy;
        unpack2(tx, ty, tE);
        unpack2(ux, uy, tO);
        accx += fmaxf(tx + ux + g.x, 0.f);
        accy += fmaxf(ty + uy + g.y, 0.f);
        if (dn != d) {
            asm volatile("red.global.add.v2.f32 [%0], {%1,%2};"
                         :: "l"(agg + (size_t)d * HD + ch), "f"(accx), "f"(accy) : "memory");
            accx = 0.f; accy = 0.f;
        }
    }
}

// ---------------------------------------------------------------------------
// FFMA GEMM (R5/R1, proven ~91% of FFMA roofline)
// ---------------------------------------------------------------------------
template<int K, int ACT, bool ADD>
__global__ __launch_bounds__(256)
void gemm_kernel(const float* __restrict__ In, const float* __restrict__ In2,
                 const float* __restrict__ W, const float* __restrict__ bias,
                 float* __restrict__ Out)
{
    __shared__ float sIn[64 * K];
    __shared__ float sW[16 * 128];
    int tid = threadIdx.x;
    int row0 = blockIdx.x * 64;

    const float4* inp  = (const float4*)(In  + (size_t)row0 * K);
    const float4* inp2 = (const float4*)(In2 + (size_t)row0 * K);
    for (int i = tid; i < (64 * K) / 4; i += 256) {
        float4 v = inp[i];
        if (ADD) {
            float4 u = inp2[i];
            v.x += u.x; v.y += u.y; v.z += u.z; v.w += u.w;
        }
        ((float4*)sIn)[i] = v;
    }

    int cx = tid & 31;
    int ry = tid >> 5;
    float4 b4 = ((const float4*)bias)[cx];
    float4 acc[8];
    #pragma unroll
    for (int m = 0; m < 8; m++) acc[m] = b4;

    for (int kc = 0; kc < K; kc += 16) {
        __syncthreads();
        for (int i = tid; i < (16 * 128) / 4; i += 256)
            ((float4*)sW)[i] = ((const float4*)(W + (size_t)kc * 128))[i];
        __syncthreads();
        #pragma unroll
        for (int k = 0; k < 16; k++) {
            float4 w = ((float4*)sW)[k * 32 + cx];
            #pragma unroll
            for (int m = 0; m < 8; m++) {
                float a = sIn[(ry * 8 + m) * K + (kc + k)];
                acc[m].x += a * w.x; acc[m].y += a * w.y;
                acc[m].z += a * w.z; acc[m].w += a * w.w;
            }
        }
    }

    #pragma unroll
    for (int m = 0; m < 8; m++) {
        float4 v = acc[m];
        if (ACT == 0) {
            v.x = leakyf(v.x); v.y = leakyf(v.y); v.z = leakyf(v.z); v.w = leakyf(v.w);
        } else {
            v.x = fmaxf(v.x, 0.f); v.y = fmaxf(v.y, 0.f);
            v.z = fmaxf(v.z, 0.f); v.w = fmaxf(v.w, 0.f);
        }
        *(float4*)(Out + (size_t)(row0 + ry * 8 + m) * 128 + cx * 4) = v;
    }
}

// ---------------------------------------------------------------------------
__global__ void pool_kernel(const float* __restrict__ h2, float* __restrict__ pooled, int Nper)
{
    int b = blockIdx.x;
    int tid = threadIdx.x;
    int c = tid & 127, half = tid >> 7;
    float s = 0.f;
    const float* base = h2 + (size_t)b * Nper * HD + c;
    for (int i = half; i < Nper; i += 2) s += base[(size_t)i * HD];
    __shared__ float sm[256];
    sm[tid] = s;
    __syncthreads();
    if (half == 0) pooled[b * HD + c] = (sm[c] + sm[128 + c]) / (float)Nper;
}

__global__ void action_kernel(const float* __restrict__ pooled,
                              const float* __restrict__ w1, const float* __restrict__ b1,
                              const float* __restrict__ w2, const float* __restrict__ b2,
                              float* __restrict__ out)
{
    __shared__ float sp[128], s1[128], s2[10];
    int b = blockIdx.x;
    int tid = threadIdx.x;
    sp[tid] = pooled[b * 128 + tid];
    __syncthreads();
    float acc = b1[tid];
    #pragma unroll 8
    for (int k = 0; k < 128; k++) acc += sp[k] * w1[k * 128 + tid];
    s1[tid] = leakyf(acc);
    __syncthreads();
    if (tid < 10) {
        float a2 = b2[tid];
        #pragma unroll 8
        for (int k = 0; k < 128; k++) a2 += s1[k] * w2[k * 10 + tid];
        s2[tid] = leakyf(a2);
    }
    __syncthreads();
    if (tid == 0) {
        float mx = -1e30f;
        for (int j = 0; j < 10; j++) mx = fmaxf(mx, s2[j]);
        float ex[10], sum = 0.f;
        for (int j = 0; j < 10; j++) { ex[j] = expf(s2[j] - mx); sum += ex[j]; }
        float inv = 1.f / sum;
        for (int j = 0; j < 10; j++) out[b * 10 + j] = ex[j] * inv;
    }
}

__global__ void score_kernel(const float* __restrict__ nh, const float* __restrict__ w3,
                             const float* __restrict__ b3, float* __restrict__ out,
                             int N, int Nper)
{
    int r = blockIdx.x * 8 + (threadIdx.x >> 5);
    int lane = threadIdx.x & 31;
    if (r >= N) return;
    float4 v = *(const float4*)(nh + (size_t)r * HD + lane * 4);
    float4 w = *(const float4*)(w3 + lane * 4);
    float acc = v.x * w.x + v.y * w.y + v.z * w.z + v.w * w.w;
    #pragma unroll
    for (int o = 16; o; o >>= 1) acc += __shfl_xor_sync(0xffffffffu, acc, o);
    if (lane == 0) {
        float z = acc + b3[0];
        out[(size_t)(r & 63) * Nper + (r >> 6)] = 1.f / (1.f + expf(-z));
    }
}

// ---------------------------------------------------------------------------
extern "C" void kernel_launch(void* const* d_in, const int* in_sizes, int n_in,
                              void* d_out, int out_size)
{
    const float* x     = (const float*)d_in[0];
    const int*   ei    = (const int*)  d_in[1];
    const float* ea    = (const float*)d_in[2];
    const float* e1_w  = (const float*)d_in[3];
    const float* e1_b  = (const float*)d_in[4];
    const float* c1_w1 = (const float*)d_in[5];
    const float* c1_b1 = (const float*)d_in[6];
    const float* c1_w2 = (const float*)d_in[7];
    const float* c1_b2 = (const float*)d_in[8];
    const float* e2_w  = (const float*)d_in[9];
    const float* e2_b  = (const float*)d_in[10];
    const float* c2_w1 = (const float*)d_in[11];
    const float* c2_b1 = (const float*)d_in[12];
    const float* c2_w2 = (const float*)d_in[13];
    const float* c2_b2 = (const float*)d_in[14];
    const float* a_w1  = (const float*)d_in[15];
    const float* a_b1  = (const float*)d_in[16];
    const float* a_w2  = (const float*)d_in[17];
    const float* a_b2  = (const float*)d_in[18];
    const float* n_w1  = (const float*)d_in[19];
    const float* n_b1  = (const float*)d_in[20];
    const float* n_w2  = (const float*)d_in[21];
    const float* n_b2  = (const float*)d_in[22];
    const float* n_w3  = (const float*)d_in[23];
    const float* n_b3  = (const float*)d_in[24];

    int N = in_sizes[0] / 32;
    int E = in_sizes[1] / 2;
    int Nper = N / 64;
    const int* src = ei;
    const int* dst = ei + E;

    int *deg, *rowptr, *cursor, *bsum, *ssrc, *sdst;
    float *eas, *agg1, *h, *agg2, *h2, *t1, *pooled;
    cudaGetSymbolAddress((void**)&deg,    g_deg);
    cudaGetSymbolAddress((void**)&rowptr, g_rowptr);
    cudaGetSymbolAddress((void**)&cursor, g_cursor);
    cudaGetSymbolAddress((void**)&bsum,   g_bsum);
    cudaGetSymbolAddress((void**)&ssrc,   g_ssrc);
    cudaGetSymbolAddress((void**)&sdst,   g_sdst);
    cudaGetSymbolAddress((void**)&eas,    g_eas);
    cudaGetSymbolAddress((void**)&agg1,   g_agg1);
    cudaGetSymbolAddress((void**)&h,      g_h);
    cudaGetSymbolAddress((void**)&agg2,   g_agg2);
    cudaGetSymbolAddress((void**)&h2,     g_h2);
    cudaGetSymbolAddress((void**)&t1,     g_t1);
    cudaGetSymbolAddress((void**)&pooled, g_pooled);

    float* out = (float*)d_out;

    int nb = (N + 255) / 256;
    int ztotal = N * 32 / 4 + N * 128 / 4 + N / 4;

    // launches 0..4: zero + CSR build (payload-permuting scatter)
    zero_all <<<(ztotal + 255) / 256, 256>>>(deg, agg1, agg2, N);
    hist_k   <<<(E + 255) / 256, 256>>>(dst, deg, E);
    scan1_k  <<<nb, 256>>>(deg, rowptr, bsum, N);
    scan23_k <<<nb, 256>>>(rowptr, bsum, cursor, N, nb);
    scatter_k<<<(E + 255) / 256, 256>>>(src, dst, ea, cursor, ssrc, sdst, eas, E);

    // launch 5: edge1  <-- ncu -s 5 profiles this
    edge1_kernel<<<(E / E1_CHUNK + 7) / 8, 256>>>(x, ssrc, sdst, eas, e1_w, e1_b, agg1, E);
    gemm_kernel<32, 0, true ><<<N / 64, 256>>>(x,  agg1, c1_w1, c1_b1, t1);
    gemm_kernel<128, 1, false><<<N / 64, 256>>>(t1, t1,   c1_w2, c1_b2, h);   // relu

    // GINE layer 2
    edge2_kernel<<<(2 * (E / E2_CHUNK) + 7) / 8, 256>>>(h, ssrc, sdst, eas, e2_w, e2_b, agg2, E);
    gemm_kernel<128, 0, true ><<<N / 64, 256>>>(h,  agg2, c2_w1, c2_b1, t1);
    gemm_kernel<128, 0, false><<<N / 64, 256>>>(t1, t1,   c2_w2, c2_b2, h2);

    // Action head
    pool_kernel<<<64, 256>>>(h2, pooled, Nper);
    action_kernel<<<64, 128>>>(pooled, a_w1, a_b1, a_w2, a_b2, out);

    // Node score head (reuse agg2 as nh2)
    gemm_kernel<128, 0, false><<<N / 64, 256>>>(h2, h2, n_w1, n_b1, t1);
    gemm_kernel<128, 0, false><<<N / 64, 256>>>(t1, t1, n_w2, n_b2, agg2);
    score_kernel<<<(N + 7) / 8, 256>>>(agg2, n_w3, n_b3, out + 640, N, Nper);
}

// round 15
// speedup vs baseline: 1.6929x; 1.6929x over previous
#include <cuda_runtime.h>
#include <math.h>
#include <stdint.h>

#define NMAX 65536
#define HD   128

typedef unsigned long long u64;

// Scratch (device globals: no allocation allowed in kernel_launch)
__device__ float g_agg1[NMAX * 32];
__device__ float g_h   [NMAX * HD];
__device__ float g_agg2[NMAX * HD];   // reused as nh2 buffer at the end
__device__ float g_h2  [NMAX * HD];
__device__ float g_t1  [NMAX * HD];
__device__ float g_pooled[64 * HD];

__device__ __forceinline__ float leakyf(float v) { return v > 0.f ? v : 0.01f * v; }

__device__ __forceinline__ u64 pack2(float lo, float hi) {
    u64 r; asm("mov.b64 %0, {%1, %2};" : "=l"(r) : "f"(lo), "f"(hi)); return r;
}
__device__ __forceinline__ void unpack2(float& lo, float& hi, u64 v) {
    asm("mov.b64 {%0, %1}, %2;" : "=f"(lo), "=f"(hi) : "l"(v));
}
__device__ __forceinline__ u64 fma2(u64 a, u64 b, u64 c) {
    u64 d; asm("fma.rn.f32x2 %0, %1, %2, %3;" : "=l"(d) : "l"(a), "l"(b), "l"(c)); return d;
}

// ---------------------------------------------------------------------------
// Edge layer 1: msg = relu(x[src] + ea @ e1_w + b); red-add into agg1 [N,32]
// One warp / 32 edges; lane owns 1 of 32 channels. W in regs.
// ea broadcast via warp-uniform LDG.128 (1 wavefront) instead of 16 shfl.
// ---------------------------------------------------------------------------
#define E1_CHUNK 32
__global__ __launch_bounds__(256)
void edge1_kernel(const float* __restrict__ x, const int* __restrict__ src,
                  const int* __restrict__ dst, const float* __restrict__ ea,
                  const float* __restrict__ W, const float* __restrict__ bias,
                  float* __restrict__ agg, int E)
{
    int lane = threadIdx.x & 31;
    int warp = blockIdx.x * 8 + (threadIdx.x >> 5);
    int base = warp * E1_CHUNK;
    if (base >= E) return;

    float w[16];
    #pragma unroll
    for (int k = 0; k < 16; k++) w[k] = __ldg(&W[k * 32 + lane]);
    float b = __ldg(&bias[lane]);

    int sA = __ldg(&src[base + lane]);
    int sD = __ldg(&dst[base + lane]);

    #pragma unroll 4
    for (int i = 0; i < E1_CHUNK; i++) {
        int e = base + i;
        int s = __shfl_sync(0xffffffffu, sA, i);
        int d = __shfl_sync(0xffffffffu, sD, i);
        float g = __ldg(&x[(size_t)s * 32 + lane]);
        const float4* ear = (const float4*)(ea + (size_t)e * 16);
        float t0 = b, t1 = 0.f;
        #pragma unroll
        for (int q = 0; q < 4; q++) {
            float4 a = __ldg(&ear[q]);   // warp-uniform address: broadcast load
            t0 = fmaf(a.x, w[q * 4 + 0], t0);
            t1 = fmaf(a.y, w[q * 4 + 1], t1);
            t0 = fmaf(a.z, w[q * 4 + 2], t0);
            t1 = fmaf(a.w, w[q * 4 + 3], t1);
        }
        float m = fmaxf(t0 + t1 + g, 0.f);
        asm volatile("red.global.add.f32 [%0], %1;"
                     :: "l"(agg + (size_t)d * 32 + lane), "f"(m) : "memory");
    }
}

// ---------------------------------------------------------------------------
// Edge layer 2: msg = relu(h[src] + ea @ e2_w + b); red-add into agg2 [N,128]
// Two warps / 16-edge chunk; warp owns 64 channels (lane = 2 ch), W as f32x2.
// ea broadcast via warp-uniform LDG.128 (4 wf/edge) instead of 16 shfl.
// ---------------------------------------------------------------------------
#define E2_CHUNK 16
__global__ __launch_bounds__(256, 4)
void edge2_kernel(const float* __restrict__ h, const int* __restrict__ src,
                  const int* __restrict__ dst, const float* __restrict__ ea,
                  const float* __restrict__ W, const float* __restrict__ bias,
                  float* __restrict__ agg, int E)
{
    int lane = threadIdx.x & 31;
    int warp = blockIdx.x * 8 + (threadIdx.x >> 5);
    int chunk = warp >> 1;
    int half  = warp & 1;
    int base = chunk * E2_CHUNK;
    if (base >= E) return;
    int ch = half * 64 + lane * 2;

    u64 w2[16];
    #pragma unroll
    for (int k = 0; k < 16; k++) {
        float2 wv = *(const float2*)(W + (size_t)k * 128 + ch);
        w2[k] = pack2(wv.x, wv.y);
    }
    float2 bv = *(const float2*)(bias + ch);
    u64 b2 = pack2(bv.x, bv.y);

    // lanes 0..15 hold src indices of the chunk, lanes 16..31 hold dst indices
    int li = lane & 15;
    int sd = (lane < 16) ? __ldg(&src[base + li]) : __ldg(&dst[base + li]);

    for (int i = 0; i < E2_CHUNK; i++) {
        int e = base + i;
        int s = __shfl_sync(0xffffffffu, sd, i);
        int d = __shfl_sync(0xffffffffu, sd, 16 + i);
        float2 g = *(const float2*)(h + (size_t)s * HD + ch);
        const float4* ear = (const float4*)(ea + (size_t)e * 16);

        u64 tE = b2, tO = 0ull;   // even-k / odd-k chains
        #pragma unroll
        for (int q = 0; q < 4; q++) {
            float4 a = __ldg(&ear[q]);   // warp-uniform address: broadcast load
            tE = fma2(pack2(a.x, a.x), w2[q * 4 + 0], tE);
            tO = fma2(pack2(a.y, a.y), w2[q * 4 + 1], tO);
            tE = fma2(pack2(a.z, a.z), w2[q * 4 + 2], tE);
            tO = fma2(pack2(a.w, a.w), w2[q * 4 + 3], tO);
        }
        float tx, ty, ux, uy;
        unpack2(tx, ty, tE);
        unpack2(ux, uy, tO);
        float mx = fmaxf(tx + ux + g.x, 0.f);
        float my = fmaxf(ty + uy + g.y, 0.f);
        asm volatile("red.global.add.v2.f32 [%0], {%1,%2};"
                     :: "l"(agg + (size_t)d * HD + ch), "f"(mx), "f"(my) : "memory");
    }
}

// ---------------------------------------------------------------------------
// FFMA GEMM (R5/R1, proven ~91% of FFMA roofline)
// ---------------------------------------------------------------------------
template<int K, int ACT, bool ADD>
__global__ __launch_bounds__(256)
void gemm_kernel(const float* __restrict__ In, const float* __restrict__ In2,
                 const float* __restrict__ W, const float* __restrict__ bias,
                 float* __restrict__ Out)
{
    __shared__ float sIn[64 * K];
    __shared__ float sW[16 * 128];
    int tid = threadIdx.x;
    int row0 = blockIdx.x * 64;

    const float4* inp  = (const float4*)(In  + (size_t)row0 * K);
    const float4* inp2 = (const float4*)(In2 + (size_t)row0 * K);
    for (int i = tid; i < (64 * K) / 4; i += 256) {
        float4 v = inp[i];
        if (ADD) {
            float4 u = inp2[i];
            v.x += u.x; v.y += u.y; v.z += u.z; v.w += u.w;
        }
        ((float4*)sIn)[i] = v;
    }

    int cx = tid & 31;
    int ry = tid >> 5;
    float4 b4 = ((const float4*)bias)[cx];
    float4 acc[8];
    #pragma unroll
    for (int m = 0; m < 8; m++) acc[m] = b4;

    for (int kc = 0; kc < K; kc += 16) {
        __syncthreads();
        for (int i = tid; i < (16 * 128) / 4; i += 256)
            ((float4*)sW)[i] = ((const float4*)(W + (size_t)kc * 128))[i];
        __syncthreads();
        #pragma unroll
        for (int k = 0; k < 16; k++) {
            float4 w = ((float4*)sW)[k * 32 + cx];
            #pragma unroll
            for (int m = 0; m < 8; m++) {
                float a = sIn[(ry * 8 + m) * K + (kc + k)];
                acc[m].x += a * w.x; acc[m].y += a * w.y;
                acc[m].z += a * w.z; acc[m].w += a * w.w;
            }
        }
    }

    #pragma unroll
    for (int m = 0; m < 8; m++) {
        float4 v = acc[m];
        if (ACT == 0) {
            v.x = leakyf(v.x); v.y = leakyf(v.y); v.z = leakyf(v.z); v.w = leakyf(v.w);
        } else {
            v.x = fmaxf(v.x, 0.f); v.y = fmaxf(v.y, 0.f);
            v.z = fmaxf(v.z, 0.f); v.w = fmaxf(v.w, 0.f);
        }
        *(float4*)(Out + (size_t)(row0 + ry * 8 + m) * 128 + cx * 4) = v;
    }
}

// ---------------------------------------------------------------------------
__global__ void pool_kernel(const float* __restrict__ h2, float* __restrict__ pooled, int Nper)
{
    int b = blockIdx.x;
    int tid = threadIdx.x;
    int c = tid & 127, half = tid >> 7;
    float s = 0.f;
    const float* base = h2 + (size_t)b * Nper * HD + c;
    for (int i = half; i < Nper; i += 2) s += base[(size_t)i * HD];
    __shared__ float sm[256];
    sm[tid] = s;
    __syncthreads();
    if (half == 0) pooled[b * HD + c] = (sm[c] + sm[128 + c]) / (float)Nper;
}

__global__ void action_kernel(const float* __restrict__ pooled,
                              const float* __restrict__ w1, const float* __restrict__ b1,
                              const float* __restrict__ w2, const float* __restrict__ b2,
                              float* __restrict__ out)
{
    __shared__ float sp[128], s1[128], s2[10];
    int b = blockIdx.x;
    int tid = threadIdx.x;
    sp[tid] = pooled[b * 128 + tid];
    __syncthreads();
    float acc = b1[tid];
    #pragma unroll 8
    for (int k = 0; k < 128; k++) acc += sp[k] * w1[k * 128 + tid];
    s1[tid] = leakyf(acc);
    __syncthreads();
    if (tid < 10) {
        float a2 = b2[tid];
        #pragma unroll 8
        for (int k = 0; k < 128; k++) a2 += s1[k] * w2[k * 10 + tid];
        s2[tid] = leakyf(a2);
    }
    __syncthreads();
    if (tid == 0) {
        float mx = -1e30f;
        for (int j = 0; j < 10; j++) mx = fmaxf(mx, s2[j]);
        float ex[10], sum = 0.f;
        for (int j = 0; j < 10; j++) { ex[j] = expf(s2[j] - mx); sum += ex[j]; }
        float inv = 1.f / sum;
        for (int j = 0; j < 10; j++) out[b * 10 + j] = ex[j] * inv;
    }
}

__global__ void score_kernel(const float* __restrict__ nh, const float* __restrict__ w3,
                             const float* __restrict__ b3, float* __restrict__ out,
                             int N, int Nper)
{
    int r = blockIdx.x * 8 + (threadIdx.x >> 5);
    int lane = threadIdx.x & 31;
    if (r >= N) return;
    float4 v = *(const float4*)(nh + (size_t)r * HD + lane * 4);
    float4 w = *(const float4*)(w3 + lane * 4);
    float acc = v.x * w.x + v.y * w.y + v.z * w.z + v.w * w.w;
    #pragma unroll
    for (int o = 16; o; o >>= 1) acc += __shfl_xor_sync(0xffffffffu, acc, o);
    if (lane == 0) {
        float z = acc + b3[0];
        out[(size_t)(r & 63) * Nper + (r >> 6)] = 1.f / (1.f + expf(-z));
    }
}

// ---------------------------------------------------------------------------
extern "C" void kernel_launch(void* const* d_in, const int* in_sizes, int n_in,
                              void* d_out, int out_size)
{
    const float* x     = (const float*)d_in[0];
    const int*   ei    = (const int*)  d_in[1];
    const float* ea    = (const float*)d_in[2];
    const float* e1_w  = (const float*)d_in[3];
    const float* e1_b  = (const float*)d_in[4];
    const float* c1_w1 = (const float*)d_in[5];
    const float* c1_b1 = (const float*)d_in[6];
    const float* c1_w2 = (const float*)d_in[7];
    const float* c1_b2 = (const float*)d_in[8];
    const float* e2_w  = (const float*)d_in[9];
    const float* e2_b  = (const float*)d_in[10];
    const float* c2_w1 = (const float*)d_in[11];
    const float* c2_b1 = (const float*)d_in[12];
    const float* c2_w2 = (const float*)d_in[13];
    const float* c2_b2 = (const float*)d_in[14];
    const float* a_w1  = (const float*)d_in[15];
    const float* a_b1  = (const float*)d_in[16];
    const float* a_w2  = (const float*)d_in[17];
    const float* a_b2  = (const float*)d_in[18];
    const float* n_w1  = (const float*)d_in[19];
    const float* n_b1  = (const float*)d_in[20];
    const float* n_w2  = (const float*)d_in[21];
    const float* n_b2  = (const float*)d_in[22];
    const float* n_w3  = (const float*)d_in[23];
    const float* n_b3  = (const float*)d_in[24];

    int N = in_sizes[0] / 32;
    int E = in_sizes[1] / 2;
    int Nper = N / 64;
    const int* src = ei;
    const int* dst = ei + E;

    float *agg1, *h, *agg2, *h2, *t1, *pooled;
    cudaGetSymbolAddress((void**)&agg1,   g_agg1);
    cudaGetSymbolAddress((void**)&h,      g_h);
    cudaGetSymbolAddress((void**)&agg2,   g_agg2);
    cudaGetSymbolAddress((void**)&h2,     g_h2);
    cudaGetSymbolAddress((void**)&t1,     g_t1);
    cudaGetSymbolAddress((void**)&pooled, g_pooled);

    float* out = (float*)d_out;

    cudaMemsetAsync(agg1, 0, (size_t)N * 32 * sizeof(float));
    cudaMemsetAsync(agg2, 0, (size_t)N * HD * sizeof(float));

    // GINE layer 1
    edge1_kernel<<<(E / E1_CHUNK + 7) / 8, 256>>>(x, src, dst, ea, e1_w, e1_b, agg1, E);
    gemm_kernel<32, 0, true ><<<N / 64, 256>>>(x,  agg1, c1_w1, c1_b1, t1);
    gemm_kernel<128, 1, false><<<N / 64, 256>>>(t1, t1,   c1_w2, c1_b2, h);   // relu

    // GINE layer 2 (launch index 5 -> ncu captures edge2)
    edge2_kernel<<<(2 * (E / E2_CHUNK) + 7) / 8, 256>>>(h, src, dst, ea, e2_w, e2_b, agg2, E);
    gemm_kernel<128, 0, true ><<<N / 64, 256>>>(h,  agg2, c2_w1, c2_b1, t1);
    gemm_kernel<128, 0, false><<<N / 64, 256>>>(t1, t1,   c2_w2, c2_b2, h2);

    // Action head
    pool_kernel<<<64, 256>>>(h2, pooled, Nper);
    action_kernel<<<64, 128>>>(pooled, a_w1, a_b1, a_w2, a_b2, out);

    // Node score head (reuse agg2 as nh2 buffer)
    gemm_kernel<128, 0, false><<<N / 64, 256>>>(h2, h2, n_w1, n_b1, t1);
    gemm_kernel<128, 0, false><<<N / 64, 256>>>(t1, t1, n_w2, n_b2, agg2);
    score_kernel<<<(N + 7) / 8, 256>>>(agg2, n_w3, n_b3, out + 640, N, Nper);
}

// round 16
// speedup vs baseline: 1.7768x; 1.0496x over previous
#include <cuda_runtime.h>
#include <math.h>
#include <stdint.h>

#define NMAX 65536
#define HD   128

typedef unsigned long long u64;

// Scratch (device globals: no allocation allowed in kernel_launch)
__device__ float g_agg1[NMAX * 32];
__device__ float g_h   [NMAX * HD];
__device__ float g_agg2[NMAX * HD];
__device__ float g_h2  [NMAX * HD];
__device__ float g_t1  [NMAX * HD];
__device__ float g_pooled[64 * HD];

__device__ __forceinline__ float leakyf(float v) { return v > 0.f ? v : 0.01f * v; }

__device__ __forceinline__ u64 pack2(float lo, float hi) {
    u64 r; asm("mov.b64 %0, {%1, %2};" : "=l"(r) : "f"(lo), "f"(hi)); return r;
}
__device__ __forceinline__ void unpack2(float& lo, float& hi, u64 v) {
    asm("mov.b64 {%0, %1}, %2;" : "=f"(lo), "=f"(hi) : "l"(v));
}
__device__ __forceinline__ u64 fma2(u64 a, u64 b, u64 c) {
    u64 d; asm("fma.rn.f32x2 %0, %1, %2, %3;" : "=l"(d) : "l"(a), "l"(b), "l"(c)); return d;
}

// ---------------------------------------------------------------------------
// Edge layer 1 (R5 shfl version — measured best for edge1)
// ---------------------------------------------------------------------------
#define E1_CHUNK 32
__global__ __launch_bounds__(256)
void edge1_kernel(const float* __restrict__ x, const int* __restrict__ src,
                  const int* __restrict__ dst, const float* __restrict__ ea,
                  const float* __restrict__ W, const float* __restrict__ bias,
                  float* __restrict__ agg, int E)
{
    int lane = threadIdx.x & 31;
    int warp = blockIdx.x * 8 + (threadIdx.x >> 5);
    int base = warp * E1_CHUNK;
    if (base >= E) return;

    float w[16];
    #pragma unroll
    for (int k = 0; k < 16; k++) w[k] = __ldg(&W[k * 32 + lane]);
    float b = __ldg(&bias[lane]);

    int sA = __ldg(&src[base + lane]);
    int sD = __ldg(&dst[base + lane]);

    #pragma unroll 4
    for (int i = 0; i < E1_CHUNK; i++) {
        int e = base + i;
        int s = __shfl_sync(0xffffffffu, sA, i);
        int d = __shfl_sync(0xffffffffu, sD, i);
        float av = (lane < 16) ? __ldg(&ea[(size_t)e * 16 + lane]) : 0.f;
        float g = __ldg(&x[(size_t)s * 32 + lane]);
        float t = b;
        #pragma unroll
        for (int k = 0; k < 16; k++)
            t = fmaf(__shfl_sync(0xffffffffu, av, k), w[k], t);
        float m = fmaxf(t + g, 0.f);
        asm volatile("red.global.add.f32 [%0], %1;"
                     :: "l"(agg + (size_t)d * 32 + lane), "f"(m) : "memory");
    }
}

// ---------------------------------------------------------------------------
// Edge layer 2 (R14 uniform-LDG version — measured best for edge2)
// ---------------------------------------------------------------------------
#define E2_CHUNK 16
__global__ __launch_bounds__(256, 4)
void edge2_kernel(const float* __restrict__ h, const int* __restrict__ src,
                  const int* __restrict__ dst, const float* __restrict__ ea,
                  const float* __restrict__ W, const float* __restrict__ bias,
                  float* __restrict__ agg, int E)
{
    int lane = threadIdx.x & 31;
    int warp = blockIdx.x * 8 + (threadIdx.x >> 5);
    int chunk = warp >> 1;
    int half  = warp & 1;
    int base = chunk * E2_CHUNK;
    if (base >= E) return;
    int ch = half * 64 + lane * 2;

    u64 w2[16];
    #pragma unroll
    for (int k = 0; k < 16; k++) {
        float2 wv = *(const float2*)(W + (size_t)k * 128 + ch);
        w2[k] = pack2(wv.x, wv.y);
    }
    float2 bv = *(const float2*)(bias + ch);
    u64 b2 = pack2(bv.x, bv.y);

    int li = lane & 15;
    int sd = (lane < 16) ? __ldg(&src[base + li]) : __ldg(&dst[base + li]);

    for (int i = 0; i < E2_CHUNK; i++) {
        int e = base + i;
        int s = __shfl_sync(0xffffffffu, sd, i);
        int d = __shfl_sync(0xffffffffu, sd, 16 + i);
        float2 g = *(const float2*)(h + (size_t)s * HD + ch);
        const float4* ear = (const float4*)(ea + (size_t)e * 16);

        u64 tE = b2, tO = 0ull;
        #pragma unroll
        for (int q = 0; q < 4; q++) {
            float4 a = __ldg(&ear[q]);   // warp-uniform address: broadcast load
            tE = fma2(pack2(a.x, a.x), w2[q * 4 + 0], tE);
            tO = fma2(pack2(a.y, a.y), w2[q * 4 + 1], tO);
            tE = fma2(pack2(a.z, a.z), w2[q * 4 + 2], tE);
            tO = fma2(pack2(a.w, a.w), w2[q * 4 + 3], tO);
        }
        float tx, ty, ux, uy;
        unpack2(tx, ty, tE);
        unpack2(ux, uy, tO);
        float mx = fmaxf(tx + ux + g.x, 0.f);
        float my = fmaxf(ty + uy + g.y, 0.f);
        asm volatile("red.global.add.v2.f32 [%0], {%1,%2};"
                     :: "l"(agg + (size_t)d * HD + ch), "f"(mx), "f"(my) : "memory");
    }
}

// ---------------------------------------------------------------------------
// FFMA GEMM (R5 body) with fused epilogues.
// MODE: 0 = plain, 1 = also RED column-sums into aux (=pooled, graph pooling),
//       2 = score head: leaky, dot w3, sigmoid, write scores ONLY (no Out).
// ---------------------------------------------------------------------------
template<int K, int ACT, bool ADD, int MODE>
__global__ __launch_bounds__(256)
void gemm_kernel(const float* __restrict__ In, const float* __restrict__ In2,
                 const float* __restrict__ W, const float* __restrict__ bias,
                 float* __restrict__ Out, float* __restrict__ aux,
                 const float* __restrict__ w3, const float* __restrict__ b3, int Nper)
{
    __shared__ float sIn[64 * K];
    __shared__ float sW[16 * 128];
    __shared__ float cs[128];
    int tid = threadIdx.x;
    int row0 = blockIdx.x * 64;

    if (MODE == 1) { if (tid < 128) cs[tid] = 0.f; }

    const float4* inp  = (const float4*)(In  + (size_t)row0 * K);
    const float4* inp2 = (const float4*)(In2 + (size_t)row0 * K);
    for (int i = tid; i < (64 * K) / 4; i += 256) {
        float4 v = inp[i];
        if (ADD) {
            float4 u = inp2[i];
            v.x += u.x; v.y += u.y; v.z += u.z; v.w += u.w;
        }
        ((float4*)sIn)[i] = v;
    }

    int cx = tid & 31;
    int ry = tid >> 5;
    float4 b4 = ((const float4*)bias)[cx];
    float4 acc[8];
    #pragma unroll
    for (int m = 0; m < 8; m++) acc[m] = b4;

    for (int kc = 0; kc < K; kc += 16) {
        __syncthreads();
        for (int i = tid; i < (16 * 128) / 4; i += 256)
            ((float4*)sW)[i] = ((const float4*)(W + (size_t)kc * 128))[i];
        __syncthreads();
        #pragma unroll
        for (int k = 0; k < 16; k++) {
            float4 w = ((float4*)sW)[k * 32 + cx];
            #pragma unroll
            for (int m = 0; m < 8; m++) {
                float a = sIn[(ry * 8 + m) * K + (kc + k)];
                acc[m].x += a * w.x; acc[m].y += a * w.y;
                acc[m].z += a * w.z; acc[m].w += a * w.w;
            }
        }
    }

    float4 w3v = make_float4(0.f, 0.f, 0.f, 0.f);
    if (MODE == 2) w3v = ((const float4*)w3)[cx];
    float4 csum = make_float4(0.f, 0.f, 0.f, 0.f);
    float rowdot[8];

    #pragma unroll
    for (int m = 0; m < 8; m++) {
        float4 v = acc[m];
        if (ACT == 0) {
            v.x = leakyf(v.x); v.y = leakyf(v.y); v.z = leakyf(v.z); v.w = leakyf(v.w);
        } else {
            v.x = fmaxf(v.x, 0.f); v.y = fmaxf(v.y, 0.f);
            v.z = fmaxf(v.z, 0.f); v.w = fmaxf(v.w, 0.f);
        }
        if (MODE != 2)
            *(float4*)(Out + (size_t)(row0 + ry * 8 + m) * 128 + cx * 4) = v;
        if (MODE == 1) {
            csum.x += v.x; csum.y += v.y; csum.z += v.z; csum.w += v.w;
        }
        if (MODE == 2)
            rowdot[m] = v.x * w3v.x + v.y * w3v.y + v.z * w3v.z + v.w * w3v.w;
    }

    if (MODE == 1) {
        __syncthreads();   // cs zero-init complete (and all warps reached epilogue)
        atomicAdd(&cs[cx * 4 + 0], csum.x);
        atomicAdd(&cs[cx * 4 + 1], csum.y);
        atomicAdd(&cs[cx * 4 + 2], csum.z);
        atomicAdd(&cs[cx * 4 + 3], csum.w);
        __syncthreads();
        if (tid < 128) {
            int b = row0 / Nper;   // 64-row block never straddles a graph
            asm volatile("red.global.add.f32 [%0], %1;"
                         :: "l"(aux + b * 128 + tid), "f"(cs[tid]) : "memory");
        }
    }

    if (MODE == 2) {
        float bz = __ldg(&b3[0]);
        #pragma unroll
        for (int m = 0; m < 8; m++) {
            float s = rowdot[m];
            #pragma unroll
            for (int o = 16; o; o >>= 1) s += __shfl_xor_sync(0xffffffffu, s, o);
            if (cx == 0) {
                int r = row0 + ry * 8 + m;
                float z = s + bz;
                aux[(size_t)(r & 63) * Nper + (r >> 6)] = 1.f / (1.f + expf(-z));
            }
        }
    }
}

// ---------------------------------------------------------------------------
// Action head: softmax(leaky(leaky(pooled/Nper @ a_w1+b1)@a_w2+b2))
// ---------------------------------------------------------------------------
__global__ void action_kernel(const float* __restrict__ pooled,
                              const float* __restrict__ w1, const float* __restrict__ b1,
                              const float* __restrict__ w2, const float* __restrict__ b2,
                              float* __restrict__ out, int Nper)
{
    __shared__ float sp[128], s1[128], s2[10];
    int b = blockIdx.x;
    int tid = threadIdx.x;
    sp[tid] = pooled[b * 128 + tid] / (float)Nper;
    __syncthreads();
    float acc = b1[tid];
    #pragma unroll 8
    for (int k = 0; k < 128; k++) acc += sp[k] * w1[k * 128 + tid];
    s1[tid] = leakyf(acc);
    __syncthreads();
    if (tid < 10) {
        float a2 = b2[tid];
        #pragma unroll 8
        for (int k = 0; k < 128; k++) a2 += s1[k] * w2[k * 10 + tid];
        s2[tid] = leakyf(a2);
    }
    __syncthreads();
    if (tid == 0) {
        float mx = -1e30f;
        for (int j = 0; j < 10; j++) mx = fmaxf(mx, s2[j]);
        float ex[10], sum = 0.f;
        for (int j = 0; j < 10; j++) { ex[j] = expf(s2[j] - mx); sum += ex[j]; }
        float inv = 1.f / sum;
        for (int j = 0; j < 10; j++) out[b * 10 + j] = ex[j] * inv;
    }
}

// ---------------------------------------------------------------------------
extern "C" void kernel_launch(void* const* d_in, const int* in_sizes, int n_in,
                              void* d_out, int out_size)
{
    const float* x     = (const float*)d_in[0];
    const int*   ei    = (const int*)  d_in[1];
    const float* ea    = (const float*)d_in[2];
    const float* e1_w  = (const float*)d_in[3];
    const float* e1_b  = (const float*)d_in[4];
    const float* c1_w1 = (const float*)d_in[5];
    const float* c1_b1 = (const float*)d_in[6];
    const float* c1_w2 = (const float*)d_in[7];
    const float* c1_b2 = (const float*)d_in[8];
    const float* e2_w  = (const float*)d_in[9];
    const float* e2_b  = (const float*)d_in[10];
    const float* c2_w1 = (const float*)d_in[11];
    const float* c2_b1 = (const float*)d_in[12];
    const float* c2_w2 = (const float*)d_in[13];
    const float* c2_b2 = (const float*)d_in[14];
    const float* a_w1  = (const float*)d_in[15];
    const float* a_b1  = (const float*)d_in[16];
    const float* a_w2  = (const float*)d_in[17];
    const float* a_b2  = (const float*)d_in[18];
    const float* n_w1  = (const float*)d_in[19];
    const float* n_b1  = (const float*)d_in[20];
    const float* n_w2  = (const float*)d_in[21];
    const float* n_b2  = (const float*)d_in[22];
    const float* n_w3  = (const float*)d_in[23];
    const float* n_b3  = (const float*)d_in[24];

    int N = in_sizes[0] / 32;
    int E = in_sizes[1] / 2;
    int Nper = N / 64;
    const int* src = ei;
    const int* dst = ei + E;

    float *agg1, *h, *agg2, *h2, *t1, *pooled;
    cudaGetSymbolAddress((void**)&agg1,   g_agg1);
    cudaGetSymbolAddress((void**)&h,      g_h);
    cudaGetSymbolAddress((void**)&agg2,   g_agg2);
    cudaGetSymbolAddress((void**)&h2,     g_h2);
    cudaGetSymbolAddress((void**)&t1,     g_t1);
    cudaGetSymbolAddress((void**)&pooled, g_pooled);

    float* out = (float*)d_out;

    cudaMemsetAsync(agg1,   0, (size_t)N * 32 * sizeof(float));
    cudaMemsetAsync(agg2,   0, (size_t)N * HD * sizeof(float));
    cudaMemsetAsync(pooled, 0, 64 * HD * sizeof(float));

    int g64 = N / 64;

    // GINE layer 1
    edge1_kernel<<<(E / E1_CHUNK + 7) / 8, 256>>>(x, src, dst, ea, e1_w, e1_b, agg1, E);
    gemm_kernel<32, 0, true, 0><<<g64, 256>>>(x, agg1, c1_w1, c1_b1, t1,
                                              nullptr, nullptr, nullptr, Nper);
    // launch 5: first gemm128 (profiled)
    gemm_kernel<128, 1, false, 0><<<g64, 256>>>(t1, t1, c1_w2, c1_b2, h,
                                                nullptr, nullptr, nullptr, Nper);  // relu

    // GINE layer 2
    edge2_kernel<<<(2 * (E / E2_CHUNK) + 7) / 8, 256>>>(h, src, dst, ea, e2_w, e2_b, agg2, E);
    gemm_kernel<128, 0, true, 0><<<g64, 256>>>(h, agg2, c2_w1, c2_b1, t1,
                                               nullptr, nullptr, nullptr, Nper);
    // h2 + fused graph pooling
    gemm_kernel<128, 0, false, 1><<<g64, 256>>>(t1, t1, c2_w2, c2_b2, h2,
                                                pooled, nullptr, nullptr, Nper);

    // Action head (reads pooled sums, divides by Nper)
    action_kernel<<<64, 128>>>(pooled, a_w1, a_b1, a_w2, a_b2, out, Nper);

    // Node score head: nw1 GEMM, then nw2 GEMM with fused dot(w3)+sigmoid
    gemm_kernel<128, 0, false, 0><<<g64, 256>>>(h2, h2, n_w1, n_b1, t1,
                                                nullptr, nullptr, nullptr, Nper);
    gemm_kernel<128, 0, false, 2><<<g64, 256>>>(t1, t1, n_w2, n_b2, nullptr,
                                                out + 640, n_w3, n_b3, Nper);
}

// round 17
// speedup vs baseline: 2.0927x; 1.1778x over previous
#include <cuda_runtime.h>
#include <math.h>
#include <stdint.h>

#define NMAX 65536
#define HD   128

typedef unsigned long long u64;

// Scratch (device globals: no allocation allowed in kernel_launch)
__device__ float g_agg1[NMAX * 32];
__device__ float g_h   [NMAX * HD];
__device__ float g_agg2[NMAX * HD];
__device__ float g_h2  [NMAX * HD];
__device__ float g_t1  [NMAX * HD];
__device__ float g_pooled[64 * HD];

__device__ __forceinline__ float leakyf(float v) { return v > 0.f ? v : 0.01f * v; }

__device__ __forceinline__ u64 pack2(float lo, float hi) {
    u64 r; asm("mov.b64 %0, {%1, %2};" : "=l"(r) : "f"(lo), "f"(hi)); return r;
}
__device__ __forceinline__ void unpack2(float& lo, float& hi, u64 v) {
    asm("mov.b64 {%0, %1}, %2;" : "=f"(lo), "=f"(hi) : "l"(v));
}
__device__ __forceinline__ u64 fma2(u64 a, u64 b, u64 c) {
    u64 d; asm("fma.rn.f32x2 %0, %1, %2, %3;" : "=l"(d) : "l"(a), "l"(b), "l"(c)); return d;
}

// ---------------------------------------------------------------------------
// Edge layer 1: block stages ea for its 256 edges in smem (coalesced LDG ->
// STS once), then mainloop reads ea via conflict-free LDS.128 broadcasts.
// One warp / 32 edges; lane owns 1 of 32 channels. W in regs.
// ---------------------------------------------------------------------------
#define E1_CHUNK 32
__global__ __launch_bounds__(256)
void edge1_kernel(const float* __restrict__ x, const int* __restrict__ src,
                  const int* __restrict__ dst, const float* __restrict__ ea,
                  const float* __restrict__ W, const float* __restrict__ bias,
                  float* __restrict__ agg, int E)
{
    __shared__ float4 sEA[256 * 4];    // 256 edges x 16 floats = 16KB
    int tid = threadIdx.x;
    int lane = tid & 31;
    int wid = tid >> 5;
    int eblk = blockIdx.x * 256;       // block's first edge
    int base = eblk + wid * E1_CHUNK;
    if (base >= E) return;

    // stage ea: 1024 float4 over 256 threads (coalesced)
    {
        const float4* src4 = (const float4*)(ea + (size_t)eblk * 16);
        #pragma unroll
        for (int it = 0; it < 4; it++)
            sEA[it * 256 + tid] = src4[it * 256 + tid];
    }

    float w[16];
    #pragma unroll
    for (int k = 0; k < 16; k++) w[k] = __ldg(&W[k * 32 + lane]);
    float b = __ldg(&bias[lane]);

    int sA = __ldg(&src[base + lane]);
    int sD = __ldg(&dst[base + lane]);
    __syncthreads();

    #pragma unroll 4
    for (int i = 0; i < E1_CHUNK; i++) {
        int s = __shfl_sync(0xffffffffu, sA, i);
        int d = __shfl_sync(0xffffffffu, sD, i);
        float g = __ldg(&x[(size_t)s * 32 + lane]);
        const float4* ear = &sEA[(wid * E1_CHUNK + i) * 4];
        float t0 = b, t1 = 0.f;
        #pragma unroll
        for (int q = 0; q < 4; q++) {
            float4 a = ear[q];    // LDS.128 broadcast (uniform address)
            t0 = fmaf(a.x, w[q * 4 + 0], t0);
            t1 = fmaf(a.y, w[q * 4 + 1], t1);
            t0 = fmaf(a.z, w[q * 4 + 2], t0);
            t1 = fmaf(a.w, w[q * 4 + 3], t1);
        }
        float m = fmaxf(t0 + t1 + g, 0.f);
        asm volatile("red.global.add.f32 [%0], %1;"
                     :: "l"(agg + (size_t)d * 32 + lane), "f"(m) : "memory");
    }
}

// ---------------------------------------------------------------------------
// Edge layer 2: block stages ea for its 64 edges (4KB), mainloop reads ea via
// LDS.128 broadcasts. Two warps / 16-edge chunk; warp owns 64 ch (lane=2ch).
// ---------------------------------------------------------------------------
#define E2_CHUNK 16
__global__ __launch_bounds__(256, 4)
void edge2_kernel(const float* __restrict__ h, const int* __restrict__ src,
                  const int* __restrict__ dst, const float* __restrict__ ea,
                  const float* __restrict__ W, const float* __restrict__ bias,
                  float* __restrict__ agg, int E)
{
    __shared__ float4 sEA[64 * 4];     // 64 edges x 16 floats = 4KB
    int tid = threadIdx.x;
    int lane = tid & 31;
    int wid = tid >> 5;
    int eblk = blockIdx.x * 64;        // block's first edge (4 chunks)
    int base = eblk + (wid >> 1) * E2_CHUNK;
    if (base >= E) return;
    int half = wid & 1;
    int ch = half * 64 + lane * 2;

    // stage ea: 256 float4 over 256 threads (coalesced)
    sEA[tid] = ((const float4*)(ea + (size_t)eblk * 16))[tid];

    u64 w2[16];
    #pragma unroll
    for (int k = 0; k < 16; k++) {
        float2 wv = *(const float2*)(W + (size_t)k * 128 + ch);
        w2[k] = pack2(wv.x, wv.y);
    }
    float2 bv = *(const float2*)(bias + ch);
    u64 b2 = pack2(bv.x, bv.y);

    int li = lane & 15;
    int sd = (lane < 16) ? __ldg(&src[base + li]) : __ldg(&dst[base + li]);
    __syncthreads();

    int cloc = (wid >> 1) * E2_CHUNK;  // chunk-local edge offset within block
    for (int i = 0; i < E2_CHUNK; i++) {
        int s = __shfl_sync(0xffffffffu, sd, i);
        int d = __shfl_sync(0xffffffffu, sd, 16 + i);
        float2 g = *(const float2*)(h + (size_t)s * HD + ch);
        const float4* ear = &sEA[(cloc + i) * 4];

        u64 tE = b2, tO = 0ull;
        #pragma unroll
        for (int q = 0; q < 4; q++) {
            float4 a = ear[q];    // LDS.128 broadcast (uniform address)
            tE = fma2(pack2(a.x, a.x), w2[q * 4 + 0], tE);
            tO = fma2(pack2(a.y, a.y), w2[q * 4 + 1], tO);
            tE = fma2(pack2(a.z, a.z), w2[q * 4 + 2], tE);
            tO = fma2(pack2(a.w, a.w), w2[q * 4 + 3], tO);
        }
        float tx, ty, ux, uy;
        unpack2(tx, ty, tE);
        unpack2(ux, uy, tO);
        float mx = fmaxf(tx + ux + g.x, 0.f);
        float my = fmaxf(ty + uy + g.y, 0.f);
        asm volatile("red.global.add.v2.f32 [%0], {%1,%2};"
                     :: "l"(agg + (size_t)d * HD + ch), "f"(mx), "f"(my) : "memory");
    }
}

// ---------------------------------------------------------------------------
// FFMA GEMM (R5 body) with fused epilogues.
// MODE: 0 = plain, 1 = also RED column-sums into aux (=pooled, graph pooling),
//       2 = score head: leaky, dot w3, sigmoid, write scores ONLY (no Out).
// ---------------------------------------------------------------------------
template<int K, int ACT, bool ADD, int MODE>
__global__ __launch_bounds__(256)
void gemm_kernel(const float* __restrict__ In, const float* __restrict__ In2,
                 const float* __restrict__ W, const float* __restrict__ bias,
                 float* __restrict__ Out, float* __restrict__ aux,
                 const float* __restrict__ w3, const float* __restrict__ b3, int Nper)
{
    __shared__ float sIn[64 * K];
    __shared__ float sW[16 * 128];
    __shared__ float cs[128];
    int tid = threadIdx.x;
    int row0 = blockIdx.x * 64;

    if (MODE == 1) { if (tid < 128) cs[tid] = 0.f; }

    const float4* inp  = (const float4*)(In  + (size_t)row0 * K);
    const float4* inp2 = (const float4*)(In2 + (size_t)row0 * K);
    for (int i = tid; i < (64 * K) / 4; i += 256) {
        float4 v = inp[i];
        if (ADD) {
            float4 u = inp2[i];
            v.x += u.x; v.y += u.y; v.z += u.z; v.w += u.w;
        }
        ((float4*)sIn)[i] = v;
    }

    int cx = tid & 31;
    int ry = tid >> 5;
    float4 b4 = ((const float4*)bias)[cx];
    float4 acc[8];
    #pragma unroll
    for (int m = 0; m < 8; m++) acc[m] = b4;

    for (int kc = 0; kc < K; kc += 16) {
        __syncthreads();
        for (int i = tid; i < (16 * 128) / 4; i += 256)
            ((float4*)sW)[i] = ((const float4*)(W + (size_t)kc * 128))[i];
        __syncthreads();
        #pragma unroll
        for (int k = 0; k < 16; k++) {
            float4 w = ((float4*)sW)[k * 32 + cx];
            #pragma unroll
            for (int m = 0; m < 8; m++) {
                float a = sIn[(ry * 8 + m) * K + (kc + k)];
                acc[m].x += a * w.x; acc[m].y += a * w.y;
                acc[m].z += a * w.z; acc[m].w += a * w.w;
            }
        }
    }

    float4 w3v = make_float4(0.f, 0.f, 0.f, 0.f);
    if (MODE == 2) w3v = ((const float4*)w3)[cx];
    float4 csum = make_float4(0.f, 0.f, 0.f, 0.f);
    float rowdot[8];

    #pragma unroll
    for (int m = 0; m < 8; m++) {
        float4 v = acc[m];
        if (ACT == 0) {
            v.x = leakyf(v.x); v.y = leakyf(v.y); v.z = leakyf(v.z); v.w = leakyf(v.w);
        } else {
            v.x = fmaxf(v.x, 0.f); v.y = fmaxf(v.y, 0.f);
            v.z = fmaxf(v.z, 0.f); v.w = fmaxf(v.w, 0.f);
        }
        if (MODE != 2)
            *(float4*)(Out + (size_t)(row0 + ry * 8 + m) * 128 + cx * 4) = v;
        if (MODE == 1) {
            csum.x += v.x; csum.y += v.y; csum.z += v.z; csum.w += v.w;
        }
        if (MODE == 2)
            rowdot[m] = v.x * w3v.x + v.y * w3v.y + v.z * w3v.z + v.w * w3v.w;
    }

    if (MODE == 1) {
        __syncthreads();   // cs zero-init complete (and all warps reached epilogue)
        atomicAdd(&cs[cx * 4 + 0], csum.x);
        atomicAdd(&cs[cx * 4 + 1], csum.y);
        atomicAdd(&cs[cx * 4 + 2], csum.z);
        atomicAdd(&cs[cx * 4 + 3], csum.w);
        __syncthreads();
        if (tid < 128) {
            int b = row0 / Nper;   // 64-row block never straddles a graph
            asm volatile("red.global.add.f32 [%0], %1;"
                         :: "l"(aux + b * 128 + tid), "f"(cs[tid]) : "memory");
        }
    }

    if (MODE == 2) {
        float bz = __ldg(&b3[0]);
        #pragma unroll
        for (int m = 0; m < 8; m++) {
            float s = rowdot[m];
            #pragma unroll
            for (int o = 16; o; o >>= 1) s += __shfl_xor_sync(0xffffffffu, s, o);
            if (cx == 0) {
                int r = row0 + ry * 8 + m;
                float z = s + bz;
                aux[(size_t)(r & 63) * Nper + (r >> 6)] = 1.f / (1.f + expf(-z));
            }
        }
    }
}

// ---------------------------------------------------------------------------
// Action head: softmax(leaky(leaky(pooled/Nper @ a_w1+b1)@a_w2+b2))
// ---------------------------------------------------------------------------
__global__ void action_kernel(const float* __restrict__ pooled,
                              const float* __restrict__ w1, const float* __restrict__ b1,
                              const float* __restrict__ w2, const float* __restrict__ b2,
                              float* __restrict__ out, int Nper)
{
    __shared__ float sp[128], s1[128], s2[10];
    int b = blockIdx.x;
    int tid = threadIdx.x;
    sp[tid] = pooled[b * 128 + tid] / (float)Nper;
    __syncthreads();
    float acc = b1[tid];
    #pragma unroll 8
    for (int k = 0; k < 128; k++) acc += sp[k] * w1[k * 128 + tid];
    s1[tid] = leakyf(acc);
    __syncthreads();
    if (tid < 10) {
        float a2 = b2[tid];
        #pragma unroll 8
        for (int k = 0; k < 128; k++) a2 += s1[k] * w2[k * 10 + tid];
        s2[tid] = leakyf(a2);
    }
    __syncthreads();
    if (tid == 0) {
        float mx = -1e30f;
        for (int j = 0; j < 10; j++) mx = fmaxf(mx, s2[j]);
        float ex[10], sum = 0.f;
        for (int j = 0; j < 10; j++) { ex[j] = expf(s2[j] - mx); sum += ex[j]; }
        float inv = 1.f / sum;
        for (int j = 0; j < 10; j++) out[b * 10 + j] = ex[j] * inv;
    }
}

// ---------------------------------------------------------------------------
extern "C" void kernel_launch(void* const* d_in, const int* in_sizes, int n_in,
                              void* d_out, int out_size)
{
    const float* x     = (const float*)d_in[0];
    const int*   ei    = (const int*)  d_in[1];
    const float* ea    = (const float*)d_in[2];
    const float* e1_w  = (const float*)d_in[3];
    const float* e1_b  = (const float*)d_in[4];
    const float* c1_w1 = (const float*)d_in[5];
    const float* c1_b1 = (const float*)d_in[6];
    const float* c1_w2 = (const float*)d_in[7];
    const float* c1_b2 = (const float*)d_in[8];
    const float* e2_w  = (const float*)d_in[9];
    const float* e2_b  = (const float*)d_in[10];
    const float* c2_w1 = (const float*)d_in[11];
    const float* c2_b1 = (const float*)d_in[12];
    const float* c2_w2 = (const float*)d_in[13];
    const float* c2_b2 = (const float*)d_in[14];
    const float* a_w1  = (const float*)d_in[15];
    const float* a_b1  = (const float*)d_in[16];
    const float* a_w2  = (const float*)d_in[17];
    const float* a_b2  = (const float*)d_in[18];
    const float* n_w1  = (const float*)d_in[19];
    const float* n_b1  = (const float*)d_in[20];
    const float* n_w2  = (const float*)d_in[21];
    const float* n_b2  = (const float*)d_in[22];
    const float* n_w3  = (const float*)d_in[23];
    const float* n_b3  = (const float*)d_in[24];

    int N = in_sizes[0] / 32;
    int E = in_sizes[1] / 2;
    int Nper = N / 64;
    const int* src = ei;
    const int* dst = ei + E;

    float *agg1, *h, *agg2, *h2, *t1, *pooled;
    cudaGetSymbolAddress((void**)&agg1,   g_agg1);
    cudaGetSymbolAddress((void**)&h,      g_h);
    cudaGetSymbolAddress((void**)&agg2,   g_agg2);
    cudaGetSymbolAddress((void**)&h2,     g_h2);
    cudaGetSymbolAddress((void**)&t1,     g_t1);
    cudaGetSymbolAddress((void**)&pooled, g_pooled);

    float* out = (float*)d_out;

    cudaMemsetAsync(agg1,   0, (size_t)N * 32 * sizeof(float));
    cudaMemsetAsync(agg2,   0, (size_t)N * HD * sizeof(float));
    cudaMemsetAsync(pooled, 0, 64 * HD * sizeof(float));

    int g64 = N / 64;

    // GINE layer 1
    edge1_kernel<<<(E + 255) / 256, 256>>>(x, src, dst, ea, e1_w, e1_b, agg1, E);
    gemm_kernel<32, 0, true, 0><<<g64, 256>>>(x, agg1, c1_w1, c1_b1, t1,
                                              nullptr, nullptr, nullptr, Nper);
    gemm_kernel<128, 1, false, 0><<<g64, 256>>>(t1, t1, c1_w2, c1_b2, h,
                                                nullptr, nullptr, nullptr, Nper);  // relu

    // GINE layer 2
    edge2_kernel<<<(E + 63) / 64, 256>>>(h, src, dst, ea, e2_w, e2_b, agg2, E);
    gemm_kernel<128, 0, true, 0><<<g64, 256>>>(h, agg2, c2_w1, c2_b1, t1,
                                               nullptr, nullptr, nullptr, Nper);
    // h2 + fused graph pooling
    gemm_kernel<128, 0, false, 1><<<g64, 256>>>(t1, t1, c2_w2, c2_b2, h2,
                                                pooled, nullptr, nullptr, Nper);

    // Action head (reads pooled sums, divides by Nper)
    action_kernel<<<64, 128>>>(pooled, a_w1, a_b1, a_w2, a_b2, out, Nper);

    // Node score head: nw1 GEMM, then nw2 GEMM with fused dot(w3)+sigmoid
    gemm_kernel<128, 0, false, 0><<<g64, 256>>>(h2, h2, n_w1, n_b1, t1,
                                                nullptr, nullptr, nullptr, Nper);
    gemm_kernel<128, 0, false, 2><<<g64, 256>>>(t1, t1, n_w2, n_b2, nullptr,
                                                out + 640, n_w3, n_b3, Nper);
}